// round 15
// baseline (speedup 1.0000x reference)
#include <cuda_runtime.h>
#include <cuda_bf16.h>
#include <math.h>

#define BB 4
#define CC 16
#define HH 512
#define WW 1024

__device__ unsigned int g_dirs[BB * HH * WW];
__device__ double g_partial[4096];

#define ONES 0x0101010101010101ULL
typedef unsigned long long u64;

// ---------------------------------------------------------------------------
// Kernel 1: dirs (frozen R12/R13 winner).
// ---------------------------------------------------------------------------
__global__ __launch_bounds__(512, 2) void dirs_kernel(const int* __restrict__ labels) {
    __shared__ unsigned char slbl[68 * 132];
    __shared__ unsigned char lutd[65 * 65];

    const int tid = threadIdx.x;
    const int b = blockIdx.z;
    const int y0 = blockIdx.y * 64;
    const int x0 = blockIdx.x * 128;
    const int* lb = labels + b * HH * WW;

    for (int idx = tid; idx < 65 * 65; idx += 512) {
        int i = idx / 65, j = idx - i * 65;
        float gxxf = (float)(i - 32);
        float gyyf = (float)(j - 32);
        float t = gyyf / (gxxf + 7.6293945e-6f);
        float at = fabsf(t);
        int d;
        if (at < 0.32491970f)      d = 0;
        else if (at < 1.37638190f) d = (t > 0.0f) ? 1 : 0;
        else                       d = (t > 0.0f) ? 2 : 3;
        lutd[idx] = (unsigned char)d;
    }

    for (int i = tid; i < 68 * 132; i += 512) {
        int r = i / 132, c = i - r * 132;
        int gy = min(max(y0 - 2 + r, 0), HH - 1);
        int gx = min(max(x0 - 2 + c, 0), WW - 1);
        slbl[i] = (unsigned char)(lb[gy * WW + gx] & 15);
    }
    __syncthreads();

    const int half = tid >> 8;
    const int hid  = tid & 255;
    const int px = hid & 127;
    const int tg = hid >> 7;
    const int j0 = tg * 32;

    u64 Sr[5], D2r[5], Er[5];

#define HROW(HR, SLOT)                                                          \
    do {                                                                        \
        const unsigned char* _row = &slbl[(HR) * 132 + px];                     \
        u64 o[5];                                                               \
        _Pragma("unroll")                                                       \
        for (int q = 0; q < 5; q++) {                                           \
            int l = _row[q];                                                    \
            u64 bit = 1ULL << ((l & 7) * 8);                                    \
            o[q] = ((l >> 3) == half) ? bit : 0ULL;                             \
        }                                                                       \
        Sr[SLOT]  = o[0] + o[4] + ((o[1] + o[3]) << 2) + (o[2] << 2) + (o[2] << 1); \
        D2r[SLOT] = o[0] + o[4] + ((ONES - o[2]) << 1);                         \
        Er[SLOT]  = (o[3] << 1) + o[4] + 3 * ONES - (o[0] + (o[1] << 1));       \
    } while (0)

    #pragma unroll
    for (int s = 0; s < 5; s++) HROW(j0 + s, s);

    unsigned short* gd = (unsigned short*)g_dirs;
    const int pixbase = (b * HH + y0) * WW + x0 + px;

    #pragma unroll
    for (int j = 0; j < 32; j++) {
        const int w0 = (j + 0) % 5, w1 = (j + 1) % 5, w2 = (j + 2) % 5;
        const int w3 = (j + 3) % 5, w4 = (j + 4) % 5;

        u64 gxx = D2r[w0] + D2r[w4] + ((D2r[w1] + D2r[w3]) << 2)
                + (D2r[w2] << 2) + (D2r[w2] << 1);
        u64 gyy = Sr[w0] + Sr[w4] + 32 * ONES - (Sr[w2] << 1);
        u64 gxy = (Er[w3] << 1) + Er[w4] + 18 * ONES - (Er[w0] + (Er[w1] << 1));

        unsigned int word = 0u;
        #pragma unroll
        for (int hw = 0; hw < 2; hw++) {
            unsigned int gxx4 = (unsigned int)(gxx >> (32 * hw));
            unsigned int gyy4 = (unsigned int)(gyy >> (32 * hw));
            unsigned int gxy4 = (unsigned int)(gxy >> (32 * hw));
            unsigned int m = __vcmpgtu4(gxy4, 0x12121212u);
            unsigned int flip = __vsub4(0x40404040u, gyy4);
            unsigned int jj4 = (flip & m) | (gyy4 & ~m);
            #pragma unroll
            for (int c = 0; c < 4; c++) {
                unsigned int gxxb = (gxx4 >> (8 * c)) & 255u;
                unsigned int jjb  = (jj4 >> (8 * c)) & 255u;
                word += ((unsigned int)lutd[gxxb * 65 + jjb]) << (2 * (4 * hw + c));
            }
        }
        gd[(pixbase + (j0 + j) * WW) * 2 + half] = (unsigned short)word;

        if (j < 31) HROW(j0 + j + 5, j % 5);
    }
#undef HROW
}

// ---------------------------------------------------------------------------
// Kernel 2: NMS sum. 256-thread blocks on 64x32 tiles (10.1 KB shared,
// ~4 blocks/SM), 4 classes/block, R13 math (__expf, __fdividef).
// ---------------------------------------------------------------------------
#define K2_THREADS 256
#define NST 72
#define NROWS 36
#define NCH (NROWS * 18)

__global__ __launch_bounds__(K2_THREADS) void nms_kernel(const float* __restrict__ pred) {
    __shared__ float sh[NROWS * NST];
    __shared__ double warpsum[8];

    const int tid = threadIdx.x;
    const int b  = blockIdx.z >> 2;
    const int cg = blockIdx.z & 3;        // classes 4*cg .. 4*cg+3
    const int y0 = blockIdx.y * 32;
    const int x0 = blockIdx.x * 64;
    const int px = tid & 63;
    const int py0 = tid >> 6;             // 0..3
    const int gx = x0 + px;
    const bool okx = (gx >= 2) && (gx < WW - 2);
    const bool xedge = (blockIdx.x == 0) || (blockIdx.x == (WW / 64 - 1));

    unsigned int dw[8];
    #pragma unroll
    for (int k = 0; k < 8; k++)
        dw[k] = g_dirs[(b * HH + y0 + py0 + 4 * k) * WW + gx];

    int gyoff[3], qq[3], sidx[3];
    bool val[3];
    #pragma unroll
    for (int t = 0; t < 3; t++) {
        int i = tid + K2_THREADS * t;
        val[t] = (i < NCH);
        int ii = val[t] ? i : 0;
        int r = ii / 18, q = ii - r * 18;
        int gy = min(max(y0 - 2 + r, 0), HH - 1);
        gyoff[t] = gy * WW;
        qq[t] = 4 * q;
        sidx[t] = r * NST + 4 * q;
    }

    float4 pf[3];
    const float* pbase = pred + ((long long)b * CC) * HH * WW;

#define LOADCLS(CIDX)                                                           \
    do {                                                                        \
        const float* _p = pbase + (long long)(CIDX) * HH * WW;                  \
        _Pragma("unroll")                                                       \
        for (int t = 0; t < 3; t++) {                                           \
            if (val[t]) {                                                       \
                if (!xedge) {                                                   \
                    pf[t] = *(const float4*)(_p + gyoff[t] + (x0 - 4) + qq[t]); \
                } else {                                                        \
                    int c0 = min(max(x0 - 4 + qq[t], 0), WW - 1);               \
                    int c1 = min(max(x0 - 3 + qq[t], 0), WW - 1);               \
                    int c2 = min(max(x0 - 2 + qq[t], 0), WW - 1);               \
                    int c3 = min(max(x0 - 1 + qq[t], 0), WW - 1);               \
                    pf[t].x = _p[gyoff[t] + c0];                                \
                    pf[t].y = _p[gyoff[t] + c1];                                \
                    pf[t].z = _p[gyoff[t] + c2];                                \
                    pf[t].w = _p[gyoff[t] + c3];                                \
                }                                                               \
            }                                                                   \
        }                                                                       \
    } while (0)

    LOADCLS(4 * cg);

    float accf = 0.0f;

    for (int cc = 0; cc < 4; cc++) {
        const int c = 4 * cg + cc;
        __syncthreads();
        #pragma unroll
        for (int t = 0; t < 3; t++) {
            if (val[t]) {
                float4 e;
                e.x = __expf(pf[t].x); e.y = __expf(pf[t].y);
                e.z = __expf(pf[t].z); e.w = __expf(pf[t].w);
                *(float4*)&sh[sidx[t]] = e;
            }
        }
        __syncthreads();

        if (cc < 3) LOADCLS(c + 1);

        #pragma unroll
        for (int k = 0; k < 8; k++) {
            int py = py0 + 4 * k;
            int gy = y0 + py;
            bool ok = okx && (gy >= 2) && (gy < HH - 2);
            int base = (py + 2) * NST + px + 4;
            int d = (dw[k] >> (2 * c)) & 3;
            bool p0 = (d == 0), p2 = (d == 2);
            int A = p0 ? 1 : (p2 ? NST : (NST - 1));
            int Bo = p0 ? -2 : (p2 ? -2 * NST : -(2 * NST - 1));
            float center = sh[base];
            int a0 = base + Bo;
            float denom = sh[a0] + sh[a0 + A] + sh[a0 + 2 * A] + sh[a0 + 3 * A];
            float qv = __fdividef(center, denom);
            accf += ok ? qv : 0.0f;
        }
    }
#undef LOADCLS

    double v = (double)accf;
    #pragma unroll
    for (int o = 16; o > 0; o >>= 1) v += __shfl_down_sync(0xffffffffu, v, o);
    if ((tid & 31) == 0) warpsum[tid >> 5] = v;
    __syncthreads();
    if (tid < 8) {
        double w = warpsum[tid];
        #pragma unroll
        for (int o = 4; o > 0; o >>= 1) w += __shfl_down_sync(0xffu, w, o);
        if (tid == 0) g_partial[blockIdx.x + 16 * blockIdx.y + 256 * blockIdx.z] = w;
    }
}

// ---------------------------------------------------------------------------
// Kernel 3: deterministic final reduction of 4096 partials.
// ---------------------------------------------------------------------------
__global__ void finalize_kernel(float* __restrict__ out) {
    __shared__ double s[512];
    int tid = threadIdx.x;
    double v = 0.0;
    #pragma unroll
    for (int t = 0; t < 8; t++) v += g_partial[tid + 512 * t];
    s[tid] = v;
    __syncthreads();
    for (int off = 256; off > 0; off >>= 1) {
        if (tid < off) s[tid] += s[tid + off];
        __syncthreads();
    }
    if (tid == 0) out[0] = (float)s[0];
}

extern "C" void kernel_launch(void* const* d_in, const int* in_sizes, int n_in,
                              void* d_out, int out_size) {
    const float* pred = (const float*)d_in[0];   // [4,16,512,1024] f32
    const int* labels = (const int*)d_in[1];     // [4,512,1024] int32
    float* out = (float*)d_out;

    dirs_kernel<<<dim3(8, 8, 4), 512>>>(labels);
    nms_kernel<<<dim3(16, 16, 16), 256>>>(pred);
    finalize_kernel<<<1, 512>>>(out);
}

// round 17
// speedup vs baseline: 1.0187x; 1.0187x over previous
#include <cuda_runtime.h>
#include <cuda_bf16.h>
#include <math.h>

#define BB 4
#define CC 16
#define HH 512
#define WW 1024
#define FULLM 0xffffffffu

__device__ unsigned int g_dirs[BB * HH * WW];
__device__ double g_partial[576];

#define ONES 0x0101010101010101ULL
typedef unsigned long long u64;

// ---------------------------------------------------------------------------
// Kernel 1: dirs (frozen R12/R13 winner).
// ---------------------------------------------------------------------------
__global__ __launch_bounds__(512, 2) void dirs_kernel(const int* __restrict__ labels) {
    __shared__ unsigned char slbl[68 * 132];
    __shared__ unsigned char lutd[65 * 65];

    const int tid = threadIdx.x;
    const int b = blockIdx.z;
    const int y0 = blockIdx.y * 64;
    const int x0 = blockIdx.x * 128;
    const int* lb = labels + b * HH * WW;

    for (int idx = tid; idx < 65 * 65; idx += 512) {
        int i = idx / 65, j = idx - i * 65;
        float gxxf = (float)(i - 32);
        float gyyf = (float)(j - 32);
        float t = gyyf / (gxxf + 7.6293945e-6f);
        float at = fabsf(t);
        int d;
        if (at < 0.32491970f)      d = 0;
        else if (at < 1.37638190f) d = (t > 0.0f) ? 1 : 0;
        else                       d = (t > 0.0f) ? 2 : 3;
        lutd[idx] = (unsigned char)d;
    }

    for (int i = tid; i < 68 * 132; i += 512) {
        int r = i / 132, c = i - r * 132;
        int gy = min(max(y0 - 2 + r, 0), HH - 1);
        int gx = min(max(x0 - 2 + c, 0), WW - 1);
        slbl[i] = (unsigned char)(lb[gy * WW + gx] & 15);
    }
    __syncthreads();

    const int half = tid >> 8;
    const int hid  = tid & 255;
    const int px = hid & 127;
    const int tg = hid >> 7;
    const int j0 = tg * 32;

    u64 Sr[5], D2r[5], Er[5];

#define HROW(HR, SLOT)                                                          \
    do {                                                                        \
        const unsigned char* _row = &slbl[(HR) * 132 + px];                     \
        u64 o[5];                                                               \
        _Pragma("unroll")                                                       \
        for (int q = 0; q < 5; q++) {                                           \
            int l = _row[q];                                                    \
            u64 bit = 1ULL << ((l & 7) * 8);                                    \
            o[q] = ((l >> 3) == half) ? bit : 0ULL;                             \
        }                                                                       \
        Sr[SLOT]  = o[0] + o[4] + ((o[1] + o[3]) << 2) + (o[2] << 2) + (o[2] << 1); \
        D2r[SLOT] = o[0] + o[4] + ((ONES - o[2]) << 1);                         \
        Er[SLOT]  = (o[3] << 1) + o[4] + 3 * ONES - (o[0] + (o[1] << 1));       \
    } while (0)

    #pragma unroll
    for (int s = 0; s < 5; s++) HROW(j0 + s, s);

    unsigned short* gd = (unsigned short*)g_dirs;
    const int pixbase = (b * HH + y0) * WW + x0 + px;

    #pragma unroll
    for (int j = 0; j < 32; j++) {
        const int w0 = (j + 0) % 5, w1 = (j + 1) % 5, w2 = (j + 2) % 5;
        const int w3 = (j + 3) % 5, w4 = (j + 4) % 5;

        u64 gxx = D2r[w0] + D2r[w4] + ((D2r[w1] + D2r[w3]) << 2)
                + (D2r[w2] << 2) + (D2r[w2] << 1);
        u64 gyy = Sr[w0] + Sr[w4] + 32 * ONES - (Sr[w2] << 1);
        u64 gxy = (Er[w3] << 1) + Er[w4] + 18 * ONES - (Er[w0] + (Er[w1] << 1));

        unsigned int word = 0u;
        #pragma unroll
        for (int hw = 0; hw < 2; hw++) {
            unsigned int gxx4 = (unsigned int)(gxx >> (32 * hw));
            unsigned int gyy4 = (unsigned int)(gyy >> (32 * hw));
            unsigned int gxy4 = (unsigned int)(gxy >> (32 * hw));
            unsigned int m = __vcmpgtu4(gxy4, 0x12121212u);
            unsigned int flip = __vsub4(0x40404040u, gyy4);
            unsigned int jj4 = (flip & m) | (gyy4 & ~m);
            #pragma unroll
            for (int c = 0; c < 4; c++) {
                unsigned int gxxb = (gxx4 >> (8 * c)) & 255u;
                unsigned int jjb  = (jj4 >> (8 * c)) & 255u;
                word += ((unsigned int)lutd[gxxb * 65 + jjb]) << (2 * (4 * hw + c));
            }
        }
        gd[(pixbase + (j0 + j) * WW) * 2 + half] = (unsigned short)word;

        if (j < 31) HROW(j0 + j + 5, j % 5);
    }
#undef HROW
}

// ---------------------------------------------------------------------------
// Kernel 2: warp-autonomous NMS (R16 + row-interior fix). Each warp: 60 cols
// x 32 rows, 4 classes. Register ring of 4 rows, shuffles for horizontal
// taps. No shared tile, no barriers.
// ---------------------------------------------------------------------------
__global__ __launch_bounds__(256, 4) void nms_kernel(const float* __restrict__ pred) {
    __shared__ double warpsum[8];

    const int tid  = threadIdx.x;
    const int lane = tid & 31;
    const int wid  = tid >> 5;
    const int s  = blockIdx.x;              // col strip 0..17
    const int rs = blockIdx.y * 8 + wid;    // row strip 0..15
    const int b  = blockIdx.z >> 2;
    const int cg = blockIdx.z & 3;
    const int x0 = 60 * s;
    const int y0 = 32 * rs;

    const int ca = x0 - 2 + lane;
    const int cb = x0 + 30 + lane;
    const int cal = min(max(ca, 0), WW - 1);
    const int cbl = min(cb, WW - 1);
    const bool oka = (lane >= 2) && (ca >= 2) && (ca < WW - 2);
    const bool okb = (lane <= 29) && (cb < WW - 2);

    const unsigned char* dirb = ((const unsigned char*)g_dirs) + cg;
    const size_t rowpix = (size_t)(b * HH) * WW;

    float accf = 0.0f;

    float ea[4], eb[4], p1a[4], p1b[4], m2a[4], m2b[4];

#define LOADPROC(SL, VA, VB)                                                    \
    do {                                                                        \
        ea[SL] = __expf(VA); eb[SL] = __expf(VB);                               \
        float _pa = __shfl_down_sync(FULLM, ea[SL], 1);                         \
        float _b0 = __shfl_sync(FULLM, eb[SL], 0);                              \
        p1a[SL] = (lane == 31) ? _b0 : _pa;                                     \
        p1b[SL] = __shfl_down_sync(FULLM, eb[SL], 1);                           \
        m2a[SL] = __shfl_up_sync(FULLM, ea[SL], 2);                            \
        float _ub = __shfl_up_sync(FULLM, eb[SL], 2);                          \
        float _uf = __shfl_sync(FULLM, ea[SL], lane + 30);                     \
        m2b[SL] = (lane < 2) ? _uf : _ub;                                      \
    } while (0)

    for (int cc = 0; cc < 4; cc++) {
        const float* p = pred + (size_t)(b * CC + 4 * cg + cc) * HH * WW;

        // prologue: ring rows t=0..3 (gy = y0-2+t, clamped)
        float pfa, pfb;
        {
            int gy = max(y0 - 2, 0);
            pfa = p[(size_t)gy * WW + cal];
            pfb = p[(size_t)gy * WW + cbl];
        }
        #pragma unroll
        for (int t = 0; t < 4; t++) {
            LOADPROC(t, pfa, pfb);
            int gy = min(max(y0 - 1 + t, 0), HH - 1);
            pfa = p[(size_t)gy * WW + cal];
            pfb = p[(size_t)gy * WW + cbl];
        }
        // after prologue pf holds row gy = y0+2

        #pragma unroll 4
        for (int o = 0; o < 32; o++) {
            const int s0 = o & 3, s1 = (o + 1) & 3, s2 = (o + 2) & 3, s3 = (o + 3) & 3;

            // M1 of center row (s2)
            float m1a = __shfl_up_sync(FULLM, ea[s2], 1);
            float m1b = __shfl_up_sync(FULLM, eb[s2], 1);
            float t31 = __shfl_sync(FULLM, ea[s2], 31);
            m1b = (lane == 0) ? t31 : m1b;

            float Va  = ((ea[s0] + ea[s1]) + ea[s2]) + ea[s3];
            float Vb  = ((eb[s0] + eb[s1]) + eb[s2]) + eb[s3];
            float D0a = ((m2a[s2] + m1a) + ea[s2]) + p1a[s2];
            float D0b = ((m2b[s2] + m1b) + eb[s2]) + p1b[s2];
            float Da  = ((p1a[s0] + ea[s1]) + m1a) + m2a[s3];
            float Db  = ((p1b[s0] + eb[s1]) + m1b) + m2b[s3];

            const int gy = y0 + o;
            const bool okr = (gy >= 2) && (gy < HH - 2);   // row-interior (the R16 bug fix)
            unsigned int dA = (unsigned int)(dirb[(rowpix + (size_t)gy * WW + cal) * 4] >> (2 * cc)) & 3u;
            unsigned int dB = (unsigned int)(dirb[(rowpix + (size_t)gy * WW + cbl) * 4] >> (2 * cc)) & 3u;

            float denA = (dA == 0) ? D0a : ((dA == 2) ? Va : Da);
            float denB = (dB == 0) ? D0b : ((dB == 2) ? Vb : Db);

            float qa = __fdividef(ea[s2], denA);
            float qb = __fdividef(eb[s2], denB);
            accf += (oka && okr) ? qa : 0.0f;
            accf += (okb && okr) ? qb : 0.0f;

            if (o < 31) {
                LOADPROC(s0, pfa, pfb);     // row gy = y0+o+2
                if (o < 30) {
                    int gy2 = min(y0 + o + 3, HH - 1);
                    pfa = p[(size_t)gy2 * WW + cal];
                    pfb = p[(size_t)gy2 * WW + cbl];
                }
            }
        }
    }
#undef LOADPROC

    // deterministic reduction: warp -> block slot
    double v = (double)accf;
    #pragma unroll
    for (int o = 16; o > 0; o >>= 1) v += __shfl_down_sync(FULLM, v, o);
    if (lane == 0) warpsum[wid] = v;
    __syncthreads();
    if (tid < 8) {
        double w = warpsum[tid];
        #pragma unroll
        for (int o = 4; o > 0; o >>= 1) w += __shfl_down_sync(0xffu, w, o);
        if (tid == 0)
            g_partial[blockIdx.x + 18 * (blockIdx.y + 2 * blockIdx.z)] = w;
    }
}

// ---------------------------------------------------------------------------
// Kernel 3: deterministic final reduction of 576 partials.
// ---------------------------------------------------------------------------
__global__ void finalize_kernel(float* __restrict__ out) {
    __shared__ double sm[512];
    int tid = threadIdx.x;
    double v = g_partial[tid];
    if (tid < 64) v += g_partial[512 + tid];
    sm[tid] = v;
    __syncthreads();
    for (int off = 256; off > 0; off >>= 1) {
        if (tid < off) sm[tid] += sm[tid + off];
        __syncthreads();
    }
    if (tid == 0) out[0] = (float)sm[0];
}

extern "C" void kernel_launch(void* const* d_in, const int* in_sizes, int n_in,
                              void* d_out, int out_size) {
    const float* pred = (const float*)d_in[0];   // [4,16,512,1024] f32
    const int* labels = (const int*)d_in[1];     // [4,512,1024] int32
    float* out = (float*)d_out;

    dirs_kernel<<<dim3(8, 8, 4), 512>>>(labels);
    nms_kernel<<<dim3(18, 2, 16), 256>>>(pred);
    finalize_kernel<<<1, 512>>>(out);
}